// round 6
// baseline (speedup 1.0000x reference)
#include <cuda_runtime.h>
#include <math.h>

// ChannelAttention — R6: pool (HBM-roofline, float2 pooled store) +
// MLP with float4/LDS.128 smem traffic (4x fewer crossbar ops).
// x  : [B=8, O=8, S=32, C=64, 32, 32] fp32 (512 MB)
// w1 : [8,64,64], w2 : [8,64,64] fp32
// out: [B,O,S,C] fp32

#define C_DIM   64
#define HW_DIM  1024
#define O_DIM   8
#define S_DIM   32
#define NBLK    2048            // B*O*S

// pooled (mean, max) pairs
__device__ float2 g_pool[NBLK * C_DIM];

// ---------------- Kernel A: pooling ----------------
__global__ __launch_bounds__(256, 6)
void pool_kernel(const float* __restrict__ x)
{
    const int lane = threadIdx.x & 31;
    const int gw   = blockIdx.x * 8 + (threadIdx.x >> 5);  // (blk, c) row id
    const float4* row = reinterpret_cast<const float4*>(x) + (size_t)gw * (HW_DIM / 4) + lane;

    float4 v0 = __ldcs(row + 0 * 32);
    float4 v1 = __ldcs(row + 1 * 32);
    float4 v2 = __ldcs(row + 2 * 32);
    float4 v3 = __ldcs(row + 3 * 32);
    float4 v4 = __ldcs(row + 4 * 32);
    float4 v5 = __ldcs(row + 5 * 32);
    float4 v6 = __ldcs(row + 6 * 32);
    float4 v7 = __ldcs(row + 7 * 32);

    float sa = (v0.x + v0.y) + (v0.z + v0.w);
    float sb = (v1.x + v1.y) + (v1.z + v1.w);
    float sc = (v2.x + v2.y) + (v2.z + v2.w);
    float sd = (v3.x + v3.y) + (v3.z + v3.w);
    sa += (v4.x + v4.y) + (v4.z + v4.w);
    sb += (v5.x + v5.y) + (v5.z + v5.w);
    sc += (v6.x + v6.y) + (v6.z + v6.w);
    sd += (v7.x + v7.y) + (v7.z + v7.w);

    float ma = fmaxf(fmaxf(v0.x, v0.y), fmaxf(v0.z, v0.w));
    float mb = fmaxf(fmaxf(v1.x, v1.y), fmaxf(v1.z, v1.w));
    float mc = fmaxf(fmaxf(v2.x, v2.y), fmaxf(v2.z, v2.w));
    float md = fmaxf(fmaxf(v3.x, v3.y), fmaxf(v3.z, v3.w));
    ma = fmaxf(ma, fmaxf(fmaxf(v4.x, v4.y), fmaxf(v4.z, v4.w)));
    mb = fmaxf(mb, fmaxf(fmaxf(v5.x, v5.y), fmaxf(v5.z, v5.w)));
    mc = fmaxf(mc, fmaxf(fmaxf(v6.x, v6.y), fmaxf(v6.z, v6.w)));
    md = fmaxf(md, fmaxf(fmaxf(v7.x, v7.y), fmaxf(v7.z, v7.w)));

    float s = (sa + sb) + (sc + sd);
    float m = fmaxf(fmaxf(ma, mb), fmaxf(mc, md));

    #pragma unroll
    for (int off = 16; off > 0; off >>= 1) {
        s += __shfl_xor_sync(0xFFFFFFFFu, s, off);
        m = fmaxf(m, __shfl_xor_sync(0xFFFFFFFFu, m, off));
    }
    if (lane == 0)
        g_pool[gw] = make_float2(s * (1.0f / (float)HW_DIM), m);
}

// ---------------- Kernel B: grouped MLP (LDS.128 everywhere) ----------------
// grid = 256 blocks x 512 threads; block handles 8 blks (same o).
#define WPAD  68    // 64 + 4: float4-aligned, conflict-free (272B lane stride)
#define WPAD4 17    // WPAD/4

__global__ __launch_bounds__(512, 2)
void mlp_kernel(const float* __restrict__ w1,
                const float* __restrict__ w2,
                float* __restrict__ out)
{
    __shared__ float w1s[C_DIM * WPAD];
    __shared__ float w2s[C_DIM * WPAD];
    __shared__ __align__(16) float spm[8][C_DIM];
    __shared__ __align__(16) float spx[8][C_DIM];
    __shared__ __align__(16) float shs[8][C_DIM];

    const int tid = threadIdx.x;
    const int sub = tid >> 6;                  // blk within block (0..7)
    const int n   = tid & 63;                  // output/hidden index
    const int blk = blockIdx.x * 8 + sub;
    const int o   = (blk / S_DIM) % O_DIM;     // same for all subs in block

    // ---- stage weights: float4 coalesced loads, padded float4 smem rows ----
    const float4* w1g4 = reinterpret_cast<const float4*>(w1 + (size_t)o * C_DIM * C_DIM);
    const float4* w2g4 = reinterpret_cast<const float4*>(w2 + (size_t)o * C_DIM * C_DIM);
    float4* w1s4 = reinterpret_cast<float4*>(w1s);
    float4* w2s4 = reinterpret_cast<float4*>(w2s);
    #pragma unroll
    for (int i = 0; i < 2; ++i) {
        int idx = tid + i * 512;               // 0..1023 float4s
        int r = idx >> 4, c4 = idx & 15;
        w1s4[r * WPAD4 + c4] = __ldg(w1g4 + idx);
        w2s4[r * WPAD4 + c4] = __ldg(w2g4 + idx);
    }

    // ---- stage pooled inputs (float2 coalesced) ----
    {
        float2 p = g_pool[blk * C_DIM + n];
        spm[sub][n] = p.x;
        spx[sub][n] = p.y;
    }
    __syncthreads();

    // ---- FC1 + relu: float4 LDS for weights and broadcasts ----
    {
        const float4* wr = reinterpret_cast<const float4*>(w1s) + n * WPAD4;
        const float4* p4 = reinterpret_cast<const float4*>(spm[sub]);
        const float4* q4 = reinterpret_cast<const float4*>(spx[sub]);
        float am = 0.0f, ax = 0.0f;
        #pragma unroll
        for (int c4 = 0; c4 < 16; ++c4) {
            float4 w = wr[c4];
            float4 p = p4[c4];
            float4 q = q4[c4];
            am = fmaf(w.x, p.x, am); am = fmaf(w.y, p.y, am);
            am = fmaf(w.z, p.z, am); am = fmaf(w.w, p.w, am);
            ax = fmaf(w.x, q.x, ax); ax = fmaf(w.y, q.y, ax);
            ax = fmaf(w.z, q.z, ax); ax = fmaf(w.w, q.w, ax);
        }
        shs[sub][n] = fmaxf(am, 0.0f) + fmaxf(ax, 0.0f);
    }
    __syncthreads();

    // ---- FC2 + sigmoid (single pass over summed hidden; FC2 is linear) ----
    {
        const float4* wr = reinterpret_cast<const float4*>(w2s) + n * WPAD4;
        const float4* h4 = reinterpret_cast<const float4*>(shs[sub]);
        float a = 0.0f;
        #pragma unroll
        for (int c4 = 0; c4 < 16; ++c4) {
            float4 w = wr[c4];
            float4 h = h4[c4];
            a = fmaf(w.x, h.x, a); a = fmaf(w.y, h.y, a);
            a = fmaf(w.z, h.z, a); a = fmaf(w.w, h.w, a);
        }
        out[(size_t)blk * C_DIM + n] = 1.0f / (1.0f + __expf(-a));
    }
}

extern "C" void kernel_launch(void* const* d_in, const int* in_sizes, int n_in,
                              void* d_out, int out_size)
{
    const float* x  = (const float*)d_in[0];
    const float* w1 = (const float*)d_in[1];
    const float* w2 = (const float*)d_in[2];
    float* out = (float*)d_out;

    pool_kernel<<<NBLK * C_DIM / 8, 256>>>(x);
    mlp_kernel<<<NBLK / 8, 512>>>(w1, w2, out);
}

// round 7
// speedup vs baseline: 1.0170x; 1.0170x over previous
#include <cuda_runtime.h>
#include <math.h>

// ChannelAttention — R7: single fused kernel, last-CTA MLP tail.
// x  : [B=8, O=8, S=32, C=64, 32, 32] fp32 (512 MB, streamed once at ~7 TB/s)
// w1 : [8,64,64], w2 : [8,64,64] fp32
// out: [B,O,S,C] fp32
//
// Grid = 16384 CTAs x 256 threads. CTA = 8 warps = 8 channel-rows of one blk;
// 8 CTAs cover one blk's 64 channels. Last-arriving CTA (atomic counter) runs
// the grouped MLP for that blk, overlapped with other CTAs' HBM streaming.

#define C_DIM   64
#define HW_DIM  1024
#define O_DIM   8
#define S_DIM   32
#define NBLK    2048            // B*O*S
#define WPAD    68              // float4-aligned padded weight row
#define WPAD4   17

__device__ float2       g_pool[NBLK * C_DIM];
__device__ unsigned int g_cnt[NBLK];      // zero-init; self-resets each launch

__global__ __launch_bounds__(256, 5)
void fused_kernel(const float* __restrict__ x,
                  const float* __restrict__ w1,
                  const float* __restrict__ w2,
                  float* __restrict__ out)
{
    __shared__ float w1s[C_DIM * WPAD];
    __shared__ float w2s[C_DIM * WPAD];
    __shared__ __align__(16) float spm[C_DIM];
    __shared__ __align__(16) float spx[C_DIM];
    __shared__ __align__(16) float shs[C_DIM];
    __shared__ int sLast;

    const int tid  = threadIdx.x;
    const int lane = tid & 31;
    const int wid  = tid >> 5;                 // 8 warps
    const int gw   = blockIdx.x * 8 + wid;     // global row id = blk*64 + c
    const int blk  = blockIdx.x >> 3;          // 8 CTAs per blk

    // ---------------- pooling: one warp per channel row ----------------
    const float4* row = reinterpret_cast<const float4*>(x) + (size_t)gw * (HW_DIM / 4) + lane;

    float4 v0 = __ldcs(row + 0 * 32);
    float4 v1 = __ldcs(row + 1 * 32);
    float4 v2 = __ldcs(row + 2 * 32);
    float4 v3 = __ldcs(row + 3 * 32);
    float4 v4 = __ldcs(row + 4 * 32);
    float4 v5 = __ldcs(row + 5 * 32);
    float4 v6 = __ldcs(row + 6 * 32);
    float4 v7 = __ldcs(row + 7 * 32);

    float sa = (v0.x + v0.y) + (v0.z + v0.w);
    float sb = (v1.x + v1.y) + (v1.z + v1.w);
    float sc = (v2.x + v2.y) + (v2.z + v2.w);
    float sd = (v3.x + v3.y) + (v3.z + v3.w);
    sa += (v4.x + v4.y) + (v4.z + v4.w);
    sb += (v5.x + v5.y) + (v5.z + v5.w);
    sc += (v6.x + v6.y) + (v6.z + v6.w);
    sd += (v7.x + v7.y) + (v7.z + v7.w);

    float ma = fmaxf(fmaxf(v0.x, v0.y), fmaxf(v0.z, v0.w));
    float mb = fmaxf(fmaxf(v1.x, v1.y), fmaxf(v1.z, v1.w));
    float mc = fmaxf(fmaxf(v2.x, v2.y), fmaxf(v2.z, v2.w));
    float md = fmaxf(fmaxf(v3.x, v3.y), fmaxf(v3.z, v3.w));
    ma = fmaxf(ma, fmaxf(fmaxf(v4.x, v4.y), fmaxf(v4.z, v4.w)));
    mb = fmaxf(mb, fmaxf(fmaxf(v5.x, v5.y), fmaxf(v5.z, v5.w)));
    mc = fmaxf(mc, fmaxf(fmaxf(v6.x, v6.y), fmaxf(v6.z, v6.w)));
    md = fmaxf(md, fmaxf(fmaxf(v7.x, v7.y), fmaxf(v7.z, v7.w)));

    float s = (sa + sb) + (sc + sd);
    float m = fmaxf(fmaxf(ma, mb), fmaxf(mc, md));

    #pragma unroll
    for (int off = 16; off > 0; off >>= 1) {
        s += __shfl_xor_sync(0xFFFFFFFFu, s, off);
        m = fmaxf(m, __shfl_xor_sync(0xFFFFFFFFu, m, off));
    }
    if (lane == 0)
        g_pool[gw] = make_float2(s * (1.0f / (float)HW_DIM), m);
    __syncthreads();

    // ---------------- last-CTA election ----------------
    if (tid == 0) {
        __threadfence();                        // release pooled writes
        unsigned int old = atomicAdd(&g_cnt[blk], 1u);
        if (old == 7u) { sLast = 1; g_cnt[blk] = 0u; }   // self-reset for replay
        else           { sLast = 0; }
    }
    __syncthreads();
    if (!sLast) return;

    // ---------------- MLP tail (only 1 of 8 CTAs per blk) ----------------
    const int o = (blk / S_DIM) % O_DIM;

    // stage pooled values (L2-fresh; bypass L1 for cross-CTA visibility)
    if (tid < C_DIM) {
        float2 p = __ldcg(&g_pool[blk * C_DIM + tid]);
        spm[tid] = p.x;
        spx[tid] = p.y;
    }

    // stage weights: coalesced float4 loads into padded smem rows
    const float4* w1g4 = reinterpret_cast<const float4*>(w1 + (size_t)o * C_DIM * C_DIM);
    const float4* w2g4 = reinterpret_cast<const float4*>(w2 + (size_t)o * C_DIM * C_DIM);
    float4* w1s4 = reinterpret_cast<float4*>(w1s);
    float4* w2s4 = reinterpret_cast<float4*>(w2s);
    #pragma unroll
    for (int i = 0; i < 4; ++i) {
        int idx = tid + i * 256;                // 0..1023 float4s
        int r = idx >> 4, c4 = idx & 15;
        w1s4[r * WPAD4 + c4] = __ldg(w1g4 + idx);
        w2s4[r * WPAD4 + c4] = __ldg(w2g4 + idx);
    }
    __syncthreads();

    // FC1 + relu
    if (tid < C_DIM) {
        const float4* wr = reinterpret_cast<const float4*>(w1s) + tid * WPAD4;
        const float4* p4 = reinterpret_cast<const float4*>(spm);
        const float4* q4 = reinterpret_cast<const float4*>(spx);
        float am = 0.0f, ax = 0.0f;
        #pragma unroll
        for (int c4 = 0; c4 < 16; ++c4) {
            float4 w = wr[c4];
            float4 p = p4[c4];
            float4 q = q4[c4];
            am = fmaf(w.x, p.x, am); am = fmaf(w.y, p.y, am);
            am = fmaf(w.z, p.z, am); am = fmaf(w.w, p.w, am);
            ax = fmaf(w.x, q.x, ax); ax = fmaf(w.y, q.y, ax);
            ax = fmaf(w.z, q.z, ax); ax = fmaf(w.w, q.w, ax);
        }
        shs[tid] = fmaxf(am, 0.0f) + fmaxf(ax, 0.0f);
    }
    __syncthreads();

    // FC2 + sigmoid (FC2 linear => single pass over summed hidden)
    if (tid < C_DIM) {
        const float4* wr = reinterpret_cast<const float4*>(w2s) + tid * WPAD4;
        const float4* h4 = reinterpret_cast<const float4*>(shs);
        float a = 0.0f;
        #pragma unroll
        for (int c4 = 0; c4 < 16; ++c4) {
            float4 w = wr[c4];
            float4 h = h4[c4];
            a = fmaf(w.x, h.x, a); a = fmaf(w.y, h.y, a);
            a = fmaf(w.z, h.z, a); a = fmaf(w.w, h.w, a);
        }
        out[(size_t)blk * C_DIM + tid] = 1.0f / (1.0f + __expf(-a));
    }
}

extern "C" void kernel_launch(void* const* d_in, const int* in_sizes, int n_in,
                              void* d_out, int out_size)
{
    const float* x  = (const float*)d_in[0];
    const float* w1 = (const float*)d_in[1];
    const float* w2 = (const float*)d_in[2];
    float* out = (float*)d_out;

    fused_kernel<<<NBLK * 8, 256>>>(x, w1, w2, out);
}

// round 8
// speedup vs baseline: 1.0250x; 1.0078x over previous
#include <cuda_runtime.h>
#include <math.h>

// ChannelAttention — R8: fused last-CTA kernel, smem-slimmed tail for occ=6.
// x  : [B=8, O=8, S=32, C=64, 32, 32] fp32 (512 MB streamed once)
// w1 : [8,64,64], w2 : [8,64,64] fp32
// out: [B,O,S,C] fp32
//
// Grid = 16384 CTAs x 256 threads (8 warps = 8 channel rows; 8 CTAs per blk).
// Last CTA per blk (atomic) runs the MLP tail. Weight staging reuses ONE
// smem buffer (w1 then w2) so smem ~18 KB -> 6 CTAs/SM for streaming depth.

#define C_DIM   64
#define HW_DIM  1024
#define O_DIM   8
#define S_DIM   32
#define NBLK    2048            // B*O*S
#define WPAD    68              // float4-aligned padded weight row
#define WPAD4   17

__device__ float2       g_pool[NBLK * C_DIM];
__device__ unsigned int g_cnt[NBLK];      // zero-init; self-resets each launch

__global__ __launch_bounds__(256, 6)
void fused_kernel(const float* __restrict__ x,
                  const float* __restrict__ w1,
                  const float* __restrict__ w2,
                  float* __restrict__ out)
{
    __shared__ float ws[C_DIM * WPAD];         // staged w1, then reused for w2
    __shared__ __align__(16) float spm[C_DIM];
    __shared__ __align__(16) float spx[C_DIM];
    __shared__ __align__(16) float shs[C_DIM];
    __shared__ int sLast;

    const int tid  = threadIdx.x;
    const int lane = tid & 31;
    const int wid  = tid >> 5;                 // 8 warps
    const int gw   = blockIdx.x * 8 + wid;     // global row id = blk*64 + c
    const int blk  = blockIdx.x >> 3;          // 8 CTAs per blk

    // ---------------- pooling: one warp per channel row ----------------
    const float4* row = reinterpret_cast<const float4*>(x) + (size_t)gw * (HW_DIM / 4) + lane;

    float4 v0 = __ldcs(row + 0 * 32);
    float4 v1 = __ldcs(row + 1 * 32);
    float4 v2 = __ldcs(row + 2 * 32);
    float4 v3 = __ldcs(row + 3 * 32);
    float4 v4 = __ldcs(row + 4 * 32);
    float4 v5 = __ldcs(row + 5 * 32);
    float4 v6 = __ldcs(row + 6 * 32);
    float4 v7 = __ldcs(row + 7 * 32);

    float sa = (v0.x + v0.y) + (v0.z + v0.w);
    float sb = (v1.x + v1.y) + (v1.z + v1.w);
    float sc = (v2.x + v2.y) + (v2.z + v2.w);
    float sd = (v3.x + v3.y) + (v3.z + v3.w);
    sa += (v4.x + v4.y) + (v4.z + v4.w);
    sb += (v5.x + v5.y) + (v5.z + v5.w);
    sc += (v6.x + v6.y) + (v6.z + v6.w);
    sd += (v7.x + v7.y) + (v7.z + v7.w);

    float ma = fmaxf(fmaxf(v0.x, v0.y), fmaxf(v0.z, v0.w));
    float mb = fmaxf(fmaxf(v1.x, v1.y), fmaxf(v1.z, v1.w));
    float mc = fmaxf(fmaxf(v2.x, v2.y), fmaxf(v2.z, v2.w));
    float md = fmaxf(fmaxf(v3.x, v3.y), fmaxf(v3.z, v3.w));
    ma = fmaxf(ma, fmaxf(fmaxf(v4.x, v4.y), fmaxf(v4.z, v4.w)));
    mb = fmaxf(mb, fmaxf(fmaxf(v5.x, v5.y), fmaxf(v5.z, v5.w)));
    mc = fmaxf(mc, fmaxf(fmaxf(v6.x, v6.y), fmaxf(v6.z, v6.w)));
    md = fmaxf(md, fmaxf(fmaxf(v7.x, v7.y), fmaxf(v7.z, v7.w)));

    float s = (sa + sb) + (sc + sd);
    float m = fmaxf(fmaxf(ma, mb), fmaxf(mc, md));

    #pragma unroll
    for (int off = 16; off > 0; off >>= 1) {
        s += __shfl_xor_sync(0xFFFFFFFFu, s, off);
        m = fmaxf(m, __shfl_xor_sync(0xFFFFFFFFu, m, off));
    }
    if (lane == 0)
        g_pool[gw] = make_float2(s * (1.0f / (float)HW_DIM), m);
    __syncthreads();

    // ---------------- last-CTA election ----------------
    if (tid == 0) {
        __threadfence();                        // release pooled writes
        unsigned int old = atomicAdd(&g_cnt[blk], 1u);
        if (old == 7u) { sLast = 1; g_cnt[blk] = 0u; }   // self-reset for replay
        else           { sLast = 0; }
    }
    __syncthreads();
    if (!sLast) return;

    // ---------------- MLP tail (1 of 8 CTAs per blk) ----------------
    const int o = (blk / S_DIM) % O_DIM;
    float4* ws4 = reinterpret_cast<float4*>(ws);

    // pooled values (bypass L1 for cross-CTA visibility)
    if (tid < C_DIM) {
        float2 p = __ldcg(&g_pool[blk * C_DIM + tid]);
        spm[tid] = p.x;
        spx[tid] = p.y;
    }

    // stage w1 (coalesced float4 -> padded rows)
    const float4* w1g4 = reinterpret_cast<const float4*>(w1 + (size_t)o * C_DIM * C_DIM);
    #pragma unroll
    for (int i = 0; i < 4; ++i) {
        int idx = tid + i * 256;                // 0..1023 float4s
        ws4[(idx >> 4) * WPAD4 + (idx & 15)] = __ldg(w1g4 + idx);
    }
    __syncthreads();

    // FC1 + relu
    if (tid < C_DIM) {
        const float4* wr = ws4 + tid * WPAD4;
        const float4* p4 = reinterpret_cast<const float4*>(spm);
        const float4* q4 = reinterpret_cast<const float4*>(spx);
        float am = 0.0f, ax = 0.0f;
        #pragma unroll
        for (int c4 = 0; c4 < 16; ++c4) {
            float4 w = wr[c4];
            float4 p = p4[c4];
            float4 q = q4[c4];
            am = fmaf(w.x, p.x, am); am = fmaf(w.y, p.y, am);
            am = fmaf(w.z, p.z, am); am = fmaf(w.w, p.w, am);
            ax = fmaf(w.x, q.x, ax); ax = fmaf(w.y, q.y, ax);
            ax = fmaf(w.z, q.z, ax); ax = fmaf(w.w, q.w, ax);
        }
        shs[tid] = fmaxf(am, 0.0f) + fmaxf(ax, 0.0f);
    }
    __syncthreads();                            // FC1 done reading ws

    // stage w2 into the SAME buffer
    const float4* w2g4 = reinterpret_cast<const float4*>(w2 + (size_t)o * C_DIM * C_DIM);
    #pragma unroll
    for (int i = 0; i < 4; ++i) {
        int idx = tid + i * 256;
        ws4[(idx >> 4) * WPAD4 + (idx & 15)] = __ldg(w2g4 + idx);
    }
    __syncthreads();

    // FC2 + sigmoid (FC2 linear => single pass over summed hidden)
    if (tid < C_DIM) {
        const float4* wr = ws4 + tid * WPAD4;
        const float4* h4 = reinterpret_cast<const float4*>(shs);
        float a = 0.0f;
        #pragma unroll
        for (int c4 = 0; c4 < 16; ++c4) {
            float4 w = wr[c4];
            float4 h = h4[c4];
            a = fmaf(w.x, h.x, a); a = fmaf(w.y, h.y, a);
            a = fmaf(w.z, h.z, a); a = fmaf(w.w, h.w, a);
        }
        out[(size_t)blk * C_DIM + tid] = 1.0f / (1.0f + __expf(-a));
    }
}

extern "C" void kernel_launch(void* const* d_in, const int* in_sizes, int n_in,
                              void* d_out, int out_size)
{
    const float* x  = (const float*)d_in[0];
    const float* w1 = (const float*)d_in[1];
    const float* w2 = (const float*)d_in[2];
    float* out = (float*)d_out;

    fused_kernel<<<NBLK * 8, 256>>>(x, w1, w2, out);
}